// round 8
// baseline (speedup 1.0000x reference)
#include <cuda_runtime.h>
#include <cuda_fp16.h>
#include <cstdint>

// ---------------------------------------------------------------------------
// Problem dims
// ---------------------------------------------------------------------------
#define BB   8192
#define KTOT 19000
#define SD   256
#define PDD  128
#define PP   16
#define DD   64

// GEMM tiling: BM=128 x BN=256, BK=32, 512 threads (16 warps 4m x 4n),
// warp tile 32x64. Stream-K over 148 CTAs.
#define BM 128
#define BK 32
#define KT_PER_M 594             // ceil(19000/32)
#define MT (BB / BM)             // 64 m-tiles
#define TOTW (MT * KT_PER_M)     // 38016 k-tile work units
#define GRID_GEMM 148
#define PERC 257                 // ceil(38036/148); 148*257 = 38036 >= TOTW
#define NSLOT 4                  // max fragments per m-tile

#define A_ST 40                  // A smem stride (floats)
#define B_STH 40                 // B smem stride (halves)
#define STAGE_A_BYTES (BM * A_ST * 4)       // 20480
#define STAGE_B_BYTES (SD * B_STH * 2)      // 20480
#define STAGE_BYTES   (STAGE_A_BYTES + STAGE_B_BYTES)   // 40960
#define SMEM_GEMM     (4 * STAGE_BYTES)                 // 163840

// ---------------------------------------------------------------------------
// Device globals (no allocations; zero-initialized at load)
// ---------------------------------------------------------------------------
__device__ __half g_w1t[(size_t)SD * KTOT];          // W1^T fp16 [n][k]
__device__ float  g_hp[NSLOT][(size_t)BB * SD];      // stream-K partials
__device__ float  g_wpt[(size_t)PP * PDD * SD];      // Wp transposed [p][d][s]

// ---------------------------------------------------------------------------
// helpers
// ---------------------------------------------------------------------------
__device__ __forceinline__ uint32_t smem_u32(const void* p) {
    uint32_t a;
    asm("{ .reg .u64 t; cvta.to.shared.u64 t, %1; cvt.u32.u64 %0, t; }" : "=r"(a) : "l"(p));
    return a;
}
__device__ __forceinline__ uint32_t pack_f16x2(float hi, float lo) {
    uint32_t r;
    asm("cvt.rn.f16x2.f32 %0, %1, %2;" : "=r"(r) : "f"(hi), "f"(lo));
    return r;
}
__device__ __forceinline__ void cp_async16(uint32_t dst, const void* src, bool valid) {
    int sz = valid ? 16 : 0;
    asm volatile("cp.async.cg.shared.global [%0], [%1], 16, %2;\n"
                 :: "r"(dst), "l"(src), "r"(sz));
}
#define CP_COMMIT() asm volatile("cp.async.commit_group;" ::: "memory")
#define CP_WAIT2()  asm volatile("cp.async.wait_group 2;" ::: "memory")

__device__ __forceinline__ void mma_f16(float* c, const uint32_t* a, const uint32_t* b) {
    asm volatile(
        "mma.sync.aligned.m16n8k16.row.col.f32.f16.f16.f32 "
        "{%0,%1,%2,%3}, {%4,%5,%6,%7}, {%8,%9}, {%0,%1,%2,%3};"
        : "+f"(c[0]), "+f"(c[1]), "+f"(c[2]), "+f"(c[3])
        : "r"(a[0]), "r"(a[1]), "r"(a[2]), "r"(a[3]), "r"(b[0]), "r"(b[1]));
}
__device__ __forceinline__ void ldmatrix_x4(uint32_t* r, uint32_t addr) {
    asm volatile("ldmatrix.sync.aligned.m8n8.x4.shared.b16 {%0,%1,%2,%3}, [%4];"
                 : "=r"(r[0]), "=r"(r[1]), "=r"(r[2]), "=r"(r[3]) : "r"(addr));
}

// ---------------------------------------------------------------------------
// Kernel 0a: W1 [K][N] f32 -> g_w1t [N][K] fp16
// ---------------------------------------------------------------------------
__global__ void transpose_w1_kernel(const float* __restrict__ W1) {
    __shared__ __half tile[32][33];
    const int k0 = blockIdx.x * 32;
    const int n0 = blockIdx.y * 32;
    const int tx = threadIdx.x, ty = threadIdx.y;
#pragma unroll
    for (int j = 0; j < 4; j++) {
        int k = k0 + ty + j * 8;
        float v = (k < KTOT) ? W1[(size_t)k * SD + n0 + tx] : 0.f;
        tile[ty + j * 8][tx] = __float2half_rn(v);
    }
    __syncthreads();
    int k = k0 + tx;
    if (k < KTOT) {
#pragma unroll
        for (int j = 0; j < 4; j++)
            g_w1t[(size_t)(n0 + ty + j * 8) * KTOT + k] = tile[tx][ty + j * 8];
    }
}

// ---------------------------------------------------------------------------
// Kernel 0b: Wp [p][s][d] -> g_wpt [p][d][s]
// ---------------------------------------------------------------------------
__global__ void transpose_wp_kernel(const float* __restrict__ Wp) {
    __shared__ float tile[32][33];
    const int s0 = blockIdx.x * 32;
    const int d0 = blockIdx.y * 32;
    const int p  = blockIdx.z;
    const int tx = threadIdx.x, ty = threadIdx.y;
#pragma unroll
    for (int j = 0; j < 4; j++)
        tile[ty + j * 8][tx] = Wp[((size_t)p * SD + s0 + ty + j * 8) * PDD + d0 + tx];
    __syncthreads();
#pragma unroll
    for (int j = 0; j < 4; j++)
        g_wpt[((size_t)p * PDD + d0 + ty + j * 8) * SD + s0 + tx] = tile[tx][ty + j * 8];
}

// ---------------------------------------------------------------------------
// Kernel 0c: zero partial slot 3 (slots 0-2 provably always written)
// ---------------------------------------------------------------------------
__global__ void zero_slot3_kernel() {
    size_t i = (size_t)blockIdx.x * 1024 + threadIdx.x;
    ((float4*)g_hp[3])[i] = make_float4(0.f, 0.f, 0.f, 0.f);
}

// ---------------------------------------------------------------------------
// GEMM: stream-K fp16 m16n8k16. CTA c owns work units [257c, 257c+257).
// ---------------------------------------------------------------------------
#define LOAD_FRAGS_F16(As, bsb, s, a, b) do {                                  \
    const int _q2 = (lane & 3) * 2;                                            \
    _Pragma("unroll")                                                          \
    for (int mi = 0; mi < 2; mi++) {                                           \
        const int _base = (wrow + mi * 16 + (lane >> 2)) * A_ST + (s) * 16 + _q2; \
        float2 _v0 = *(const float2*)&(As)[_base];                             \
        float2 _v1 = *(const float2*)&(As)[_base + 8 * A_ST];                  \
        float2 _v2 = *(const float2*)&(As)[_base + 8];                         \
        float2 _v3 = *(const float2*)&(As)[_base + 8 * A_ST + 8];              \
        a[mi][0] = pack_f16x2(_v0.y, _v0.x);                                   \
        a[mi][1] = pack_f16x2(_v1.y, _v1.x);                                   \
        a[mi][2] = pack_f16x2(_v2.y, _v2.x);                                   \
        a[mi][3] = pack_f16x2(_v3.y, _v3.x);                                   \
    }                                                                          \
    const int _g  = lane >> 3;                                                 \
    const int _rr = lane & 7;                                                  \
    const int _nr = _rr + ((_g >> 1) << 3);                                    \
    const int _kc = (s) * 16 + ((_g & 1) << 3);                                \
    _Pragma("unroll")                                                          \
    for (int j = 0; j < 4; j++) {                                              \
        uint32_t _addr = (bsb) + ((wcol + j * 16 + _nr) * B_STH + _kc) * 2;    \
        uint32_t _r[4];                                                        \
        ldmatrix_x4(_r, _addr);                                                \
        b[2*j  ][0] = _r[0]; b[2*j  ][1] = _r[1];                              \
        b[2*j+1][0] = _r[2]; b[2*j+1][1] = _r[3];                              \
    }                                                                          \
} while (0)

__global__ __launch_bounds__(512, 1)
void gemm_f16_kernel(const float* __restrict__ x, const float* __restrict__ b1)
{
    extern __shared__ char smem[];
    const uint32_t sb = smem_u32(smem);

    const int tid  = threadIdx.x;
    const int lane = tid & 31;
    const int wid  = tid >> 5;
    const int wrow = (wid & 3) * 32;
    const int wcol = (wid >> 2) * 64;

    const int c    = blockIdx.x;
    int wbeg = c * PERC;
    const int wcap = min(wbeg + PERC, TOTW);

    while (wbeg < wcap) {
        const int m      = wbeg / KT_PER_M;
        const int kt0    = wbeg - m * KT_PER_M;
        const int fend   = min(wcap, (m + 1) * KT_PER_M);
        const int ntiles = fend - wbeg;
        const int slot   = c - (KT_PER_M * m) / PERC;
        const bool addb  = (kt0 == 0);
        const int m0     = m * BM;
        const int kstart = kt0 * BK;

        float acc[2][8][4];
#pragma unroll
        for (int mi = 0; mi < 2; mi++)
#pragma unroll
            for (int ni = 0; ni < 8; ni++)
#pragma unroll
                for (int j = 0; j < 4; j++) acc[mi][ni][j] = 0.f;

        __syncthreads();   // all warps done with previous fragment's smem

        auto load_tile = [&](int kb, int stage) {
            const uint32_t ab  = sb + stage * STAGE_BYTES;
            const uint32_t bbs = ab + STAGE_A_BYTES;
#pragma unroll
            for (int i = 0; i < 2; i++) {
                int cc  = tid + i * 512;
                int row = cc >> 3;
                int ko  = (cc & 7) << 2;
                int kg  = kb + ko;
                cp_async16(ab + row * (A_ST * 4) + ko * 4,
                           x + (size_t)(m0 + row) * KTOT + kg, kg < KTOT);
            }
#pragma unroll
            for (int i = 0; i < 2; i++) {
                int cc  = tid + i * 512;
                int row = cc >> 2;
                int ko  = (cc & 3) << 3;
                int kg  = kb + ko;
                cp_async16(bbs + (row * B_STH + ko) * 2,
                           g_w1t + (size_t)row * KTOT + kg, kg < KTOT);
            }
        };

#pragma unroll
        for (int s = 0; s < 3; s++) { load_tile(kstart + s * BK, s); CP_COMMIT(); }

        for (int t = 0; t < ntiles; t++) {
            CP_WAIT2();
            __syncthreads();

            if (t + 3 < ntiles) load_tile(kstart + (t + 3) * BK, (t + 3) & 3);
            CP_COMMIT();

            const float* As = (const float*)(smem + (t & 3) * STAGE_BYTES);
            const uint32_t bsb = sb + (t & 3) * STAGE_BYTES + STAGE_A_BYTES;

            uint32_t af[2][2][4], bf[2][8][2];
            LOAD_FRAGS_F16(As, bsb, 0, af[0], bf[0]);
#pragma unroll
            for (int s = 0; s < 2; s++) {
                if (s == 0) LOAD_FRAGS_F16(As, bsb, 1, af[1], bf[1]);
#pragma unroll
                for (int mi = 0; mi < 2; mi++)
#pragma unroll
                    for (int ni = 0; ni < 8; ni++)
                        mma_f16(acc[mi][ni], af[s][mi], bf[s][ni]);
            }
        }

        // epilogue: write this fragment's partial into its slot
        float* op = g_hp[slot];
#pragma unroll
        for (int mi = 0; mi < 2; mi++) {
            int r0 = m0 + wrow + mi * 16 + (lane >> 2);
#pragma unroll
            for (int ni = 0; ni < 8; ni++) {
                int cc = wcol + ni * 8 + (lane & 3) * 2;
                float bx = 0.f, by = 0.f;
                if (addb) { bx = __ldg(&b1[cc]); by = __ldg(&b1[cc + 1]); }
                float2 v0 = make_float2(acc[mi][ni][0] + bx, acc[mi][ni][1] + by);
                float2 v1 = make_float2(acc[mi][ni][2] + bx, acc[mi][ni][3] + by);
                *(float2*)(op + (size_t)r0 * SD + cc)       = v0;
                *(float2*)(op + (size_t)(r0 + 8) * SD + cc) = v1;
            }
        }
        wbeg = fend;
    }
}

// ---------------------------------------------------------------------------
// Kernel 2: per-sample pathway expert + drug head (transposed Wp, float4 loop)
// ---------------------------------------------------------------------------
__global__ __launch_bounds__(128)
void pathway_drug_kernel(const float* __restrict__ bp,
                         const float* __restrict__ Wd,
                         const float* __restrict__ bd,
                         const int*   __restrict__ drug_indices,
                         const int*   __restrict__ drug_to_pw,
                         float*       __restrict__ out)
{
    const int b   = blockIdx.x;
    const int tid = threadIdx.x;

    __shared__ __align__(16) float hs[SD];
    __shared__ float red[4];

    const int drug = drug_indices[b];
    const int p    = drug_to_pw[drug];

    {
        const size_t i0 = (size_t)b * SD + tid;
        float h0 = g_hp[0][i0]       + g_hp[1][i0]       + g_hp[2][i0]       + g_hp[3][i0];
        float h1 = g_hp[0][i0 + 128] + g_hp[1][i0 + 128] + g_hp[2][i0 + 128] + g_hp[3][i0 + 128];
        hs[tid]       = fmaxf(h0, 0.f);
        hs[tid + 128] = fmaxf(h1, 0.f);
    }
    __syncthreads();

    const float4* wr = (const float4*)(g_wpt + ((size_t)p * PDD + tid) * SD);
    float acc = 0.f;
#pragma unroll 16
    for (int i = 0; i < SD / 4; i++) {
        float4 w = wr[i];
        float4 h = *(const float4*)&hs[i * 4];
        acc = fmaf(w.x, h.x, acc);
        acc = fmaf(w.y, h.y, acc);
        acc = fmaf(w.z, h.z, acc);
        acc = fmaf(w.w, h.w, acc);
    }

    acc += bp[p * PDD + tid];
    acc = fmaxf(acc, 0.f);

    float v = acc * Wd[drug * PDD + tid];
#pragma unroll
    for (int off = 16; off > 0; off >>= 1)
        v += __shfl_xor_sync(0xffffffffu, v, off);
    if ((tid & 31) == 0) red[tid >> 5] = v;
    __syncthreads();
    if (tid == 0)
        out[b] = red[0] + red[1] + red[2] + red[3] + bd[drug];
}

// ---------------------------------------------------------------------------
// Launch. Inputs: x, drug_indices, W1, b1, Wp, bp, Wd, bd, drug_to_pw
// ---------------------------------------------------------------------------
extern "C" void kernel_launch(void* const* d_in, const int* in_sizes, int n_in,
                              void* d_out, int out_size)
{
    const float* x            = (const float*)d_in[0];
    const int*   drug_indices = (const int*)  d_in[1];
    const float* W1           = (const float*)d_in[2];
    const float* b1           = (const float*)d_in[3];
    const float* Wp           = (const float*)d_in[4];
    const float* bp           = (const float*)d_in[5];
    const float* Wd           = (const float*)d_in[6];
    const float* bd           = (const float*)d_in[7];
    const int*   drug_to_pw   = (const int*)  d_in[8];
    float*       out          = (float*)d_out;

    static int attr_set = 0;
    if (!attr_set) {
        cudaFuncSetAttribute(gemm_f16_kernel,
                             cudaFuncAttributeMaxDynamicSharedMemorySize, SMEM_GEMM);
        attr_set = 1;
    }

    dim3 tg1((KTOT + 31) / 32, SD / 32);
    transpose_w1_kernel<<<tg1, dim3(32, 8)>>>(W1);

    transpose_wp_kernel<<<dim3(SD / 32, PDD / 32, PP), dim3(32, 8)>>>(Wp);

    zero_slot3_kernel<<<(BB * SD / 4) / 1024, 1024>>>();

    gemm_f16_kernel<<<GRID_GEMM, 512, SMEM_GEMM>>>(x, b1);

    pathway_drug_kernel<<<BB, 128>>>(bp, Wd, bd, drug_indices, drug_to_pw, out);
}

// round 9
// speedup vs baseline: 1.5141x; 1.5141x over previous
#include <cuda_runtime.h>
#include <cuda_fp16.h>
#include <cstdint>

// ---------------------------------------------------------------------------
// Problem dims
// ---------------------------------------------------------------------------
#define BB   8192
#define KTOT 19000
#define SD   256
#define PDD  128
#define PP   16
#define DD   64

// GEMM tiling: BM=128 x BN=256, BK=32, 512 threads (16 warps 4m x 4n),
// warp tile 32x64. Stream-K over 148 CTAs.
#define BM 128
#define BK 32
#define KT_PER_M 594             // ceil(19000/32)
#define MT (BB / BM)             // 64 m-tiles
#define TOTW (MT * KT_PER_M)     // 38016 k-tile work units
#define GRID_GEMM 148
#define PERC 257                 // ceil(TOTW/148)
#define NSLOT 4

#define A_ST 40                  // A smem stride (floats)
#define B_STH 40                 // B smem stride (halves)
#define STAGE_A_BYTES (BM * A_ST * 4)       // 20480
#define STAGE_B_BYTES (SD * B_STH * 2)      // 20480
#define STAGE_BYTES   (STAGE_A_BYTES + STAGE_B_BYTES)   // 40960
#define SMEM_GEMM     (4 * STAGE_BYTES)                 // 163840

// ---------------------------------------------------------------------------
// Device globals (no allocations)
// ---------------------------------------------------------------------------
__device__ __half g_w1t[(size_t)SD * KTOT];       // W1^T fp16 [n][k]
__device__ float  g_hp[NSLOT][(size_t)BB * SD];   // stream-K partials

// ---------------------------------------------------------------------------
// helpers
// ---------------------------------------------------------------------------
__device__ __forceinline__ uint32_t smem_u32(const void* p) {
    uint32_t a;
    asm("{ .reg .u64 t; cvta.to.shared.u64 t, %1; cvt.u32.u64 %0, t; }" : "=r"(a) : "l"(p));
    return a;
}
__device__ __forceinline__ uint32_t pack_f16x2(float hi, float lo) {
    uint32_t r;
    asm("cvt.rn.f16x2.f32 %0, %1, %2;" : "=r"(r) : "f"(hi), "f"(lo));
    return r;
}
__device__ __forceinline__ void cp_async16(uint32_t dst, const void* src, bool valid) {
    int sz = valid ? 16 : 0;
    asm volatile("cp.async.cg.shared.global [%0], [%1], 16, %2;\n"
                 :: "r"(dst), "l"(src), "r"(sz));
}
#define CP_COMMIT() asm volatile("cp.async.commit_group;" ::: "memory")
#define CP_WAIT2()  asm volatile("cp.async.wait_group 2;" ::: "memory")

__device__ __forceinline__ void mma_f16(float* c, const uint32_t* a, const uint32_t* b) {
    asm volatile(
        "mma.sync.aligned.m16n8k16.row.col.f32.f16.f16.f32 "
        "{%0,%1,%2,%3}, {%4,%5,%6,%7}, {%8,%9}, {%0,%1,%2,%3};"
        : "+f"(c[0]), "+f"(c[1]), "+f"(c[2]), "+f"(c[3])
        : "r"(a[0]), "r"(a[1]), "r"(a[2]), "r"(a[3]), "r"(b[0]), "r"(b[1]));
}
__device__ __forceinline__ void ldmatrix_x4(uint32_t* r, uint32_t addr) {
    asm volatile("ldmatrix.sync.aligned.m8n8.x4.shared.b16 {%0,%1,%2,%3}, [%4];"
                 : "=r"(r[0]), "=r"(r[1]), "=r"(r[2]), "=r"(r[3]) : "r"(addr));
}

// ---------------------------------------------------------------------------
// Kernel 0: W1 [K][N] f32 -> g_w1t [N][K] fp16
// ---------------------------------------------------------------------------
__global__ void transpose_w1_kernel(const float* __restrict__ W1) {
    __shared__ __half tile[32][33];
    const int k0 = blockIdx.x * 32;
    const int n0 = blockIdx.y * 32;
    const int tx = threadIdx.x, ty = threadIdx.y;
#pragma unroll
    for (int j = 0; j < 4; j++) {
        int k = k0 + ty + j * 8;
        float v = (k < KTOT) ? W1[(size_t)k * SD + n0 + tx] : 0.f;
        tile[ty + j * 8][tx] = __float2half_rn(v);
    }
    __syncthreads();
    int k = k0 + tx;
    if (k < KTOT) {
#pragma unroll
        for (int j = 0; j < 4; j++)
            g_w1t[(size_t)(n0 + ty + j * 8) * KTOT + k] = tile[tx][ty + j * 8];
    }
}

// ---------------------------------------------------------------------------
// GEMM: stream-K fp16 m16n8k16 (identical to R8 measured-best: 321.6 us)
// ---------------------------------------------------------------------------
#define LOAD_FRAGS_F16(As, bsb, s, a, b) do {                                  \
    const int _q2 = (lane & 3) * 2;                                            \
    _Pragma("unroll")                                                          \
    for (int mi = 0; mi < 2; mi++) {                                           \
        const int _base = (wrow + mi * 16 + (lane >> 2)) * A_ST + (s) * 16 + _q2; \
        float2 _v0 = *(const float2*)&(As)[_base];                             \
        float2 _v1 = *(const float2*)&(As)[_base + 8 * A_ST];                  \
        float2 _v2 = *(const float2*)&(As)[_base + 8];                         \
        float2 _v3 = *(const float2*)&(As)[_base + 8 * A_ST + 8];              \
        a[mi][0] = pack_f16x2(_v0.y, _v0.x);                                   \
        a[mi][1] = pack_f16x2(_v1.y, _v1.x);                                   \
        a[mi][2] = pack_f16x2(_v2.y, _v2.x);                                   \
        a[mi][3] = pack_f16x2(_v3.y, _v3.x);                                   \
    }                                                                          \
    const int _g  = lane >> 3;                                                 \
    const int _rr = lane & 7;                                                  \
    const int _nr = _rr + ((_g >> 1) << 3);                                    \
    const int _kc = (s) * 16 + ((_g & 1) << 3);                                \
    _Pragma("unroll")                                                          \
    for (int j = 0; j < 4; j++) {                                              \
        uint32_t _addr = (bsb) + ((wcol + j * 16 + _nr) * B_STH + _kc) * 2;    \
        uint32_t _r[4];                                                        \
        ldmatrix_x4(_r, _addr);                                                \
        b[2*j  ][0] = _r[0]; b[2*j  ][1] = _r[1];                              \
        b[2*j+1][0] = _r[2]; b[2*j+1][1] = _r[3];                              \
    }                                                                          \
} while (0)

__global__ __launch_bounds__(512, 1)
void gemm_f16_kernel(const float* __restrict__ x, const float* __restrict__ b1)
{
    extern __shared__ char smem[];
    const uint32_t sb = smem_u32(smem);

    const int tid  = threadIdx.x;
    const int lane = tid & 31;
    const int wid  = tid >> 5;
    const int wrow = (wid & 3) * 32;
    const int wcol = (wid >> 2) * 64;

    const int c    = blockIdx.x;
    int wbeg = c * PERC;
    const int wcap = min(wbeg + PERC, TOTW);

    while (wbeg < wcap) {
        const int m      = wbeg / KT_PER_M;
        const int kt0    = wbeg - m * KT_PER_M;
        const int fend   = min(wcap, (m + 1) * KT_PER_M);
        const int ntiles = fend - wbeg;
        const int slot   = c - (KT_PER_M * m) / PERC;
        const bool addb  = (kt0 == 0);
        const int m0     = m * BM;
        const int kstart = kt0 * BK;

        float acc[2][8][4];
#pragma unroll
        for (int mi = 0; mi < 2; mi++)
#pragma unroll
            for (int ni = 0; ni < 8; ni++)
#pragma unroll
                for (int j = 0; j < 4; j++) acc[mi][ni][j] = 0.f;

        __syncthreads();

        auto load_tile = [&](int kb, int stage) {
            const uint32_t ab  = sb + stage * STAGE_BYTES;
            const uint32_t bbs = ab + STAGE_A_BYTES;
#pragma unroll
            for (int i = 0; i < 2; i++) {
                int cc  = tid + i * 512;
                int row = cc >> 3;
                int ko  = (cc & 7) << 2;
                int kg  = kb + ko;
                cp_async16(ab + row * (A_ST * 4) + ko * 4,
                           x + (size_t)(m0 + row) * KTOT + kg, kg < KTOT);
            }
#pragma unroll
            for (int i = 0; i < 2; i++) {
                int cc  = tid + i * 512;
                int row = cc >> 2;
                int ko  = (cc & 3) << 3;
                int kg  = kb + ko;
                cp_async16(bbs + (row * B_STH + ko) * 2,
                           g_w1t + (size_t)row * KTOT + kg, kg < KTOT);
            }
        };

#pragma unroll
        for (int s = 0; s < 3; s++) { load_tile(kstart + s * BK, s); CP_COMMIT(); }

        for (int t = 0; t < ntiles; t++) {
            CP_WAIT2();
            __syncthreads();

            if (t + 3 < ntiles) load_tile(kstart + (t + 3) * BK, (t + 3) & 3);
            CP_COMMIT();

            const float* As = (const float*)(smem + (t & 3) * STAGE_BYTES);
            const uint32_t bsb = sb + (t & 3) * STAGE_BYTES + STAGE_A_BYTES;

            uint32_t af[2][2][4], bf[2][8][2];
            LOAD_FRAGS_F16(As, bsb, 0, af[0], bf[0]);
#pragma unroll
            for (int s = 0; s < 2; s++) {
                if (s == 0) LOAD_FRAGS_F16(As, bsb, 1, af[1], bf[1]);
#pragma unroll
                for (int mi = 0; mi < 2; mi++)
#pragma unroll
                    for (int ni = 0; ni < 8; ni++)
                        mma_f16(acc[mi][ni], af[s][mi], bf[s][ni]);
            }
        }

        float* op = g_hp[slot];
#pragma unroll
        for (int mi = 0; mi < 2; mi++) {
            int r0 = m0 + wrow + mi * 16 + (lane >> 2);
#pragma unroll
            for (int ni = 0; ni < 8; ni++) {
                int cc = wcol + ni * 8 + (lane & 3) * 2;
                float bx = 0.f, by = 0.f;
                if (addb) { bx = __ldg(&b1[cc]); by = __ldg(&b1[cc + 1]); }
                float2 v0 = make_float2(acc[mi][ni][0] + bx, acc[mi][ni][1] + by);
                float2 v1 = make_float2(acc[mi][ni][2] + bx, acc[mi][ni][3] + by);
                *(float2*)(op + (size_t)r0 * SD + cc)       = v0;
                *(float2*)(op + (size_t)(r0 + 8) * SD + cc) = v1;
            }
        }
        wbeg = fend;
    }
}

// ---------------------------------------------------------------------------
// Kernel 2: per-sample pathway expert + drug head (R3 coalesced form).
// Slot count per m-tile derived analytically from the stream-K partition,
// so no zero-fill kernel is needed.
// ---------------------------------------------------------------------------
__global__ __launch_bounds__(128)
void pathway_drug_kernel(const float* __restrict__ Wp,
                         const float* __restrict__ bp,
                         const float* __restrict__ Wd,
                         const float* __restrict__ bd,
                         const int*   __restrict__ drug_indices,
                         const int*   __restrict__ drug_to_pw,
                         float*       __restrict__ out)
{
    const int b   = blockIdx.x;
    const int tid = threadIdx.x;

    __shared__ float hs[SD];
    __shared__ float red[4];

    const int drug = drug_indices[b];
    const int p    = drug_to_pw[drug];

    // number of stream-K fragments covering this sample's m-tile
    const int m  = b >> 7;                         // b / BM
    const int c0 = (KT_PER_M * m) / PERC;
    const int c1 = (KT_PER_M * (m + 1) - 1) / PERC;
    const int ns = c1 - c0 + 1;                    // 3 or 4

    {
        const size_t i0 = (size_t)b * SD + tid;
        float h0 = g_hp[0][i0]       + g_hp[1][i0]       + g_hp[2][i0];
        float h1 = g_hp[0][i0 + 128] + g_hp[1][i0 + 128] + g_hp[2][i0 + 128];
        if (ns == 4) { h0 += g_hp[3][i0]; h1 += g_hp[3][i0 + 128]; }
        hs[tid]       = fmaxf(h0, 0.f);
        hs[tid + 128] = fmaxf(h1, 0.f);
    }
    __syncthreads();

    const float* wcol = Wp + (size_t)p * SD * PDD + tid;
    float acc = 0.f;
#pragma unroll 8
    for (int s = 0; s < SD; s++)
        acc = fmaf(hs[s], wcol[(size_t)s * PDD], acc);

    acc += bp[p * PDD + tid];
    acc = fmaxf(acc, 0.f);

    float v = acc * Wd[drug * PDD + tid];
#pragma unroll
    for (int off = 16; off > 0; off >>= 1)
        v += __shfl_xor_sync(0xffffffffu, v, off);
    if ((tid & 31) == 0) red[tid >> 5] = v;
    __syncthreads();
    if (tid == 0)
        out[b] = red[0] + red[1] + red[2] + red[3] + bd[drug];
}

// ---------------------------------------------------------------------------
// Launch. Inputs: x, drug_indices, W1, b1, Wp, bp, Wd, bd, drug_to_pw
// ---------------------------------------------------------------------------
extern "C" void kernel_launch(void* const* d_in, const int* in_sizes, int n_in,
                              void* d_out, int out_size)
{
    const float* x            = (const float*)d_in[0];
    const int*   drug_indices = (const int*)  d_in[1];
    const float* W1           = (const float*)d_in[2];
    const float* b1           = (const float*)d_in[3];
    const float* Wp           = (const float*)d_in[4];
    const float* bp           = (const float*)d_in[5];
    const float* Wd           = (const float*)d_in[6];
    const float* bd           = (const float*)d_in[7];
    const int*   drug_to_pw   = (const int*)  d_in[8];
    float*       out          = (float*)d_out;

    static int attr_set = 0;
    if (!attr_set) {
        cudaFuncSetAttribute(gemm_f16_kernel,
                             cudaFuncAttributeMaxDynamicSharedMemorySize, SMEM_GEMM);
        attr_set = 1;
    }

    dim3 tg1((KTOT + 31) / 32, SD / 32);
    transpose_w1_kernel<<<tg1, dim3(32, 8)>>>(W1);

    gemm_f16_kernel<<<GRID_GEMM, 512, SMEM_GEMM>>>(x, b1);

    pathway_drug_kernel<<<BB, 128>>>(Wp, bp, Wd, bd, drug_indices, drug_to_pw, out);
}

// round 10
// speedup vs baseline: 1.6252x; 1.0734x over previous
#include <cuda_runtime.h>
#include <cuda_fp16.h>
#include <cstdint>

// ---------------------------------------------------------------------------
// Problem dims
// ---------------------------------------------------------------------------
#define BB   8192
#define KTOT 19000
#define SD   256
#define PDD  128
#define PP   16
#define DD   64

// GEMM tiling: BM=128 x BN=256, BK=32, 512 threads (16 warps 4m x 4n),
// warp tile 32x64. Stream-K over 148 CTAs.
#define BM 128
#define BK 32
#define KT_PER_M 594             // ceil(19000/32)
#define MT (BB / BM)             // 64
#define TOTW (MT * KT_PER_M)     // 38016
#define GRID_GEMM 148
#define PERC 257                 // ceil(TOTW/148)
#define NSLOT 4

#define A_ST 40                  // A smem stride (floats), conflict-free
#define B_BLK 16384              // one swizzled B tile block (256 n x 32 k fp16)
#define STAGE_A_BYTES (BM * A_ST * 4)            // 20480
#define STAGE_BYTES   (STAGE_A_BYTES + B_BLK)    // 36864
#define MB_OFF        (4 * STAGE_BYTES)          // mbarriers after stages
#define SMEM_GEMM     (MB_OFF + 64)              // 147520

// ---------------------------------------------------------------------------
// Device globals
// ---------------------------------------------------------------------------
__device__ __align__(1024) __half g_w1b[(size_t)KT_PER_M * (B_BLK / 2)];
__device__ float g_hp[NSLOT][(size_t)BB * SD];   // stream-K partials

// ---------------------------------------------------------------------------
// helpers
// ---------------------------------------------------------------------------
__device__ __forceinline__ uint32_t smem_u32(const void* p) {
    uint32_t a;
    asm("{ .reg .u64 t; cvta.to.shared.u64 t, %1; cvt.u32.u64 %0, t; }" : "=r"(a) : "l"(p));
    return a;
}
__device__ __forceinline__ uint32_t pack_f16x2(float hi, float lo) {
    uint32_t r;
    asm("cvt.rn.f16x2.f32 %0, %1, %2;" : "=r"(r) : "f"(hi), "f"(lo));
    return r;
}
__device__ __forceinline__ void cp_async16(uint32_t dst, const void* src, bool valid) {
    int sz = valid ? 16 : 0;
    asm volatile("cp.async.cg.shared.global [%0], [%1], 16, %2;\n"
                 :: "r"(dst), "l"(src), "r"(sz));
}
#define CP_COMMIT() asm volatile("cp.async.commit_group;" ::: "memory")
#define CP_WAIT2()  asm volatile("cp.async.wait_group 2;" ::: "memory")

__device__ __forceinline__ void cp_bulk(uint32_t dst, const void* src,
                                        uint32_t bytes, uint32_t mbar) {
    asm volatile(
        "cp.async.bulk.shared::cluster.global.mbarrier::complete_tx::bytes "
        "[%0], [%1], %2, [%3];"
        :: "r"(dst), "l"(src), "r"(bytes), "r"(mbar) : "memory");
}
#define MBAR_INIT(addr, cnt) \
    asm volatile("mbarrier.init.shared.b64 [%0], %1;" :: "r"(addr), "r"(cnt) : "memory")
#define MBAR_EXPECT(addr, n) \
    asm volatile("mbarrier.arrive.expect_tx.shared.b64 _, [%0], %1;" :: "r"(addr), "r"(n) : "memory")
#define MBAR_WAIT(addr, parity) do {                                            \
    uint32_t _m = (addr), _p = (parity), _d;                                    \
    asm volatile("{\n\t.reg .pred p;\n\t"                                       \
        "mbarrier.try_wait.parity.acquire.cta.shared::cta.b64 p, [%1], %2;\n\t" \
        "selp.b32 %0, 1, 0, p;\n\t}" : "=r"(_d) : "r"(_m), "r"(_p) : "memory"); \
    if (!_d) {                                                                  \
        asm volatile("{\n\t.reg .pred P1;\n\t"                                  \
            "W_%=:\n\t"                                                         \
            "mbarrier.try_wait.parity.acquire.cta.shared::cta.b64 P1, [%0], %1, 0x989680;\n\t" \
            "@P1 bra.uni D_%=;\n\t"                                             \
            "bra.uni W_%=;\n\t"                                                 \
            "D_%=:\n\t}" :: "r"(_m), "r"(_p) : "memory");                       \
    }                                                                           \
} while (0)

__device__ __forceinline__ void mma_f16(float* c, const uint32_t* a, const uint32_t* b) {
    asm volatile(
        "mma.sync.aligned.m16n8k16.row.col.f32.f16.f16.f32 "
        "{%0,%1,%2,%3}, {%4,%5,%6,%7}, {%8,%9}, {%0,%1,%2,%3};"
        : "+f"(c[0]), "+f"(c[1]), "+f"(c[2]), "+f"(c[3])
        : "r"(a[0]), "r"(a[1]), "r"(a[2]), "r"(a[3]), "r"(b[0]), "r"(b[1]));
}
__device__ __forceinline__ void ldmatrix_x4(uint32_t* r, uint32_t addr) {
    asm volatile("ldmatrix.sync.aligned.m8n8.x4.shared.b16 {%0,%1,%2,%3}, [%4];"
                 : "=r"(r[0]), "=r"(r[1]), "=r"(r[2]), "=r"(r[3]) : "r"(addr));
}

// ---------------------------------------------------------------------------
// Kernel 0: repack W1 [K][N] f32 -> g_w1b: per-k-tile 16KB blocks, fp16,
// pre-swizzled so an identity bulk copy lands conflict-free for ldmatrix.
// half (n,k) -> block + line(n>>1)*128 + (((n&1)*4 + k/8) ^ (line&7))*16 + (k&7)*2
// ---------------------------------------------------------------------------
__global__ void repack_w1_kernel(const float* __restrict__ W1) {
    const int kt = blockIdx.x;        // 0..593
    const int n  = threadIdx.x;       // 0..255
    const int kb = kt * BK;
    const int line = n >> 1, h = n & 1;
    char* base = (char*)g_w1b + (size_t)kt * B_BLK;
#pragma unroll
    for (int c = 0; c < 4; c++) {
        uint32_t w[4];
#pragma unroll
        for (int j = 0; j < 4; j++) {
            int k0 = kb + c * 8 + j * 2;
            float v0 = (k0     < KTOT) ? W1[(size_t)k0 * SD + n]       : 0.f;
            float v1 = (k0 + 1 < KTOT) ? W1[(size_t)(k0 + 1) * SD + n] : 0.f;
            w[j] = pack_f16x2(v1, v0);
        }
        uint32_t off = line * 128 + ((((h << 2) + c) ^ (line & 7)) << 4);
        *(uint4*)(base + off) = make_uint4(w[0], w[1], w[2], w[3]);
    }
}

// ---------------------------------------------------------------------------
// GEMM: stream-K fp16 m16n8k16; A per-thread cp.async, B one bulk copy/tile.
// ---------------------------------------------------------------------------
#define LOAD_FRAGS_F16(As, bsb, s, a, b) do {                                  \
    const int _q2 = (lane & 3) * 2;                                            \
    _Pragma("unroll")                                                          \
    for (int mi = 0; mi < 2; mi++) {                                           \
        const int _base = (wrow + mi * 16 + (lane >> 2)) * A_ST + (s) * 16 + _q2; \
        float2 _v0 = *(const float2*)&(As)[_base];                             \
        float2 _v1 = *(const float2*)&(As)[_base + 8 * A_ST];                  \
        float2 _v2 = *(const float2*)&(As)[_base + 8];                         \
        float2 _v3 = *(const float2*)&(As)[_base + 8 * A_ST + 8];              \
        a[mi][0] = pack_f16x2(_v0.y, _v0.x);                                   \
        a[mi][1] = pack_f16x2(_v1.y, _v1.x);                                   \
        a[mi][2] = pack_f16x2(_v2.y, _v2.x);                                   \
        a[mi][3] = pack_f16x2(_v3.y, _v3.x);                                   \
    }                                                                          \
    const int _g  = lane >> 3;                                                 \
    const int _nrb = (lane & 7) + ((_g >> 1) << 3);                            \
    const int _ci = (s) * 2 + (_g & 1);        /* 16B k-chunk index 0..3 */    \
    _Pragma("unroll")                                                          \
    for (int j = 0; j < 4; j++) {                                              \
        const int _n  = wcol + j * 16 + _nrb;                                  \
        const int _ln = _n >> 1;                                               \
        uint32_t _addr = (bsb) + _ln * 128 +                                   \
                         (((((_n & 1) << 2) + _ci) ^ (_ln & 7)) << 4);         \
        uint32_t _r[4];                                                        \
        ldmatrix_x4(_r, _addr);                                                \
        b[2*j  ][0] = _r[0]; b[2*j  ][1] = _r[1];                              \
        b[2*j+1][0] = _r[2]; b[2*j+1][1] = _r[3];                              \
    }                                                                          \
} while (0)

__global__ __launch_bounds__(512, 1)
void gemm_f16_kernel(const float* __restrict__ x, const float* __restrict__ b1)
{
    extern __shared__ char smem[];
    const uint32_t sb = smem_u32(smem);

    const int tid  = threadIdx.x;
    const int lane = tid & 31;
    const int wid  = tid >> 5;
    const int wrow = (wid & 3) * 32;
    const int wcol = (wid >> 2) * 64;

    if (tid == 0) {
#pragma unroll
        for (int s = 0; s < 4; s++) MBAR_INIT(sb + MB_OFF + s * 8, 1);
    }
    __syncthreads();

    const int c = blockIdx.x;
    int wbeg = c * PERC;
    const int wcap = min(wbeg + PERC, TOTW);
    int tseq = 0;   // global tile sequence (uniform): stage = seq&3, parity = (seq>>2)&1

    while (wbeg < wcap) {
        const int m      = wbeg / KT_PER_M;
        const int kt0    = wbeg - m * KT_PER_M;
        const int fend   = min(wcap, (m + 1) * KT_PER_M);
        const int nt     = fend - wbeg;
        const int slot   = c - (KT_PER_M * m) / PERC;
        const bool addb  = (kt0 == 0);
        const int m0     = m * BM;

        float acc[2][8][4];
#pragma unroll
        for (int mi = 0; mi < 2; mi++)
#pragma unroll
            for (int ni = 0; ni < 8; ni++)
#pragma unroll
                for (int j = 0; j < 4; j++) acc[mi][ni][j] = 0.f;

        __syncthreads();

        auto load_a = [&](int kt, int stage) {
            const uint32_t ab = sb + stage * STAGE_BYTES;
            const int kb = kt * BK;
#pragma unroll
            for (int i = 0; i < 2; i++) {
                int cc  = tid + i * 512;
                int row = cc >> 3;
                int ko  = (cc & 7) << 2;
                int kg  = kb + ko;
                cp_async16(ab + row * (A_ST * 4) + ko * 4,
                           x + (size_t)(m0 + row) * KTOT + kg, kg < KTOT);
            }
        };
        auto load_b = [&](int kt, int stage) {   // tid 0 only
            const uint32_t bbs = sb + stage * STAGE_BYTES + STAGE_A_BYTES;
            const uint32_t mb  = sb + MB_OFF + stage * 8;
            MBAR_EXPECT(mb, B_BLK);
            cp_bulk(bbs, (const char*)g_w1b + (size_t)kt * B_BLK, B_BLK, mb);
        };

        // prologue: exactly 3 commits; real loads only for i < nt
#pragma unroll
        for (int i = 0; i < 3; i++) {
            if (i < nt) load_a(kt0 + i, (tseq + i) & 3);
            CP_COMMIT();
            if (tid == 0 && i < nt) load_b(kt0 + i, (tseq + i) & 3);
        }

        for (int t = 0; t < nt; t++) {
            const int seq = tseq + t;
            MBAR_WAIT(sb + MB_OFF + (seq & 3) * 8, (seq >> 2) & 1);
            CP_WAIT2();
            __syncthreads();

            if (t + 3 < nt) load_a(kt0 + t + 3, (seq + 3) & 3);
            CP_COMMIT();
            if (tid == 0 && t + 3 < nt) load_b(kt0 + t + 3, (seq + 3) & 3);

            const int st = seq & 3;
            const float* As = (const float*)(smem + st * STAGE_BYTES);
            const uint32_t bsb = sb + st * STAGE_BYTES + STAGE_A_BYTES;

            uint32_t af[2][2][4], bf[2][8][2];
            LOAD_FRAGS_F16(As, bsb, 0, af[0], bf[0]);
#pragma unroll
            for (int s = 0; s < 2; s++) {
                if (s == 0) LOAD_FRAGS_F16(As, bsb, 1, af[1], bf[1]);
#pragma unroll
                for (int mi = 0; mi < 2; mi++)
#pragma unroll
                    for (int ni = 0; ni < 8; ni++)
                        mma_f16(acc[mi][ni], af[s][mi], bf[s][ni]);
            }
        }
        tseq += nt;

        float* op = g_hp[slot];
#pragma unroll
        for (int mi = 0; mi < 2; mi++) {
            int r0 = m0 + wrow + mi * 16 + (lane >> 2);
#pragma unroll
            for (int ni = 0; ni < 8; ni++) {
                int cc = wcol + ni * 8 + (lane & 3) * 2;
                float bx = 0.f, by = 0.f;
                if (addb) { bx = __ldg(&b1[cc]); by = __ldg(&b1[cc + 1]); }
                float2 v0 = make_float2(acc[mi][ni][0] + bx, acc[mi][ni][1] + by);
                float2 v1 = make_float2(acc[mi][ni][2] + bx, acc[mi][ni][3] + by);
                *(float2*)(op + (size_t)r0 * SD + cc)       = v0;
                *(float2*)(op + (size_t)(r0 + 8) * SD + cc) = v1;
            }
        }
        wbeg = fend;
    }
}

// ---------------------------------------------------------------------------
// Kernel 2: per-sample pathway expert + drug head (R9 proven form).
// ---------------------------------------------------------------------------
__global__ __launch_bounds__(128)
void pathway_drug_kernel(const float* __restrict__ Wp,
                         const float* __restrict__ bp,
                         const float* __restrict__ Wd,
                         const float* __restrict__ bd,
                         const int*   __restrict__ drug_indices,
                         const int*   __restrict__ drug_to_pw,
                         float*       __restrict__ out)
{
    const int b   = blockIdx.x;
    const int tid = threadIdx.x;

    __shared__ float hs[SD];
    __shared__ float red[4];

    const int drug = drug_indices[b];
    const int p    = drug_to_pw[drug];

    const int m  = b >> 7;
    const int c0 = (KT_PER_M * m) / PERC;
    const int c1 = (KT_PER_M * (m + 1) - 1) / PERC;
    const int ns = c1 - c0 + 1;

    {
        const size_t i0 = (size_t)b * SD + tid;
        float h0 = g_hp[0][i0]       + g_hp[1][i0]       + g_hp[2][i0];
        float h1 = g_hp[0][i0 + 128] + g_hp[1][i0 + 128] + g_hp[2][i0 + 128];
        if (ns == 4) { h0 += g_hp[3][i0]; h1 += g_hp[3][i0 + 128]; }
        hs[tid]       = fmaxf(h0, 0.f);
        hs[tid + 128] = fmaxf(h1, 0.f);
    }
    __syncthreads();

    const float* wcol = Wp + (size_t)p * SD * PDD + tid;
    float acc = 0.f;
#pragma unroll 8
    for (int s = 0; s < SD; s++)
        acc = fmaf(hs[s], wcol[(size_t)s * PDD], acc);

    acc += bp[p * PDD + tid];
    acc = fmaxf(acc, 0.f);

    float v = acc * Wd[drug * PDD + tid];
#pragma unroll
    for (int off = 16; off > 0; off >>= 1)
        v += __shfl_xor_sync(0xffffffffu, v, off);
    if ((tid & 31) == 0) red[tid >> 5] = v;
    __syncthreads();
    if (tid == 0)
        out[b] = red[0] + red[1] + red[2] + red[3] + bd[drug];
}

// ---------------------------------------------------------------------------
// Launch. Inputs: x, drug_indices, W1, b1, Wp, bp, Wd, bd, drug_to_pw
// ---------------------------------------------------------------------------
extern "C" void kernel_launch(void* const* d_in, const int* in_sizes, int n_in,
                              void* d_out, int out_size)
{
    const float* x            = (const float*)d_in[0];
    const int*   drug_indices = (const int*)  d_in[1];
    const float* W1           = (const float*)d_in[2];
    const float* b1           = (const float*)d_in[3];
    const float* Wp           = (const float*)d_in[4];
    const float* bp           = (const float*)d_in[5];
    const float* Wd           = (const float*)d_in[6];
    const float* bd           = (const float*)d_in[7];
    const int*   drug_to_pw   = (const int*)  d_in[8];
    float*       out          = (float*)d_out;

    static int attr_set = 0;
    if (!attr_set) {
        cudaFuncSetAttribute(gemm_f16_kernel,
                             cudaFuncAttributeMaxDynamicSharedMemorySize, SMEM_GEMM);
        attr_set = 1;
    }

    repack_w1_kernel<<<KT_PER_M, 256>>>(W1);

    gemm_f16_kernel<<<GRID_GEMM, 512, SMEM_GEMM>>>(x, b1);

    pathway_drug_kernel<<<BB, 128>>>(Wp, bp, Wd, bd, drug_indices, drug_to_pw, out);
}

// round 13
// speedup vs baseline: 1.8802x; 1.1569x over previous
#include <cuda_runtime.h>
#include <cuda_fp16.h>
#include <cstdint>

// ---------------------------------------------------------------------------
// Problem dims
// ---------------------------------------------------------------------------
#define BB   8192
#define KTOT 19000
#define SD   256
#define PDD  128
#define PP   16
#define DD   64

// GEMM tiling: BM=128 x BN=256, BK=64, 512 threads (16 warps 4m x 4n),
// warp tile 32x64. Stream-K over 148 CTAs.
#define BM 128
#define BK 64
#define KT_PER_M 297             // ceil(19000/64)
#define MT (BB / BM)             // 64
#define TOTW (MT * KT_PER_M)     // 19008
#define GRID_GEMM 148
#define PERC 129                 // ceil(TOTW/148)
#define NSLOT 4

#define A_ST 72                  // A smem stride (floats)
#define B_BLK32 16384            // one swizzled 32-k B block
#define B_BLK   32768            // per 64-k tile: two consecutive 32-k blocks
#define STAGE_A_BYTES (BM * A_ST * 4)            // 36864
#define STAGE_BYTES   (STAGE_A_BYTES + B_BLK)    // 69632
#define MB_OFF        (3 * STAGE_BYTES)          // 208896
#define SMEM_GEMM     (MB_OFF + 64)              // 208960

// ---------------------------------------------------------------------------
// Device globals
// ---------------------------------------------------------------------------
__device__ __align__(1024) __half g_w1b[(size_t)(KT_PER_M * 2) * (B_BLK32 / 2)];
__device__ float g_hp[NSLOT][(size_t)BB * SD];   // stream-K partials

// ---------------------------------------------------------------------------
// helpers
// ---------------------------------------------------------------------------
__device__ __forceinline__ uint32_t smem_u32(const void* p) {
    uint32_t a;
    asm("{ .reg .u64 t; cvta.to.shared.u64 t, %1; cvt.u32.u64 %0, t; }" : "=r"(a) : "l"(p));
    return a;
}
__device__ __forceinline__ uint32_t pack_f16x2(float hi, float lo) {
    uint32_t r;
    asm("cvt.rn.f16x2.f32 %0, %1, %2;" : "=r"(r) : "f"(hi), "f"(lo));
    return r;
}
__device__ __forceinline__ void cp_async16(uint32_t dst, const void* src, bool valid) {
    int sz = valid ? 16 : 0;
    asm volatile("cp.async.cg.shared.global [%0], [%1], 16, %2;\n"
                 :: "r"(dst), "l"(src), "r"(sz));
}
#define CP_COMMIT() asm volatile("cp.async.commit_group;" ::: "memory")
#define CP_WAIT1()  asm volatile("cp.async.wait_group 1;" ::: "memory")

__device__ __forceinline__ void cp_bulk(uint32_t dst, const void* src,
                                        uint32_t bytes, uint32_t mbar) {
    asm volatile(
        "cp.async.bulk.shared::cluster.global.mbarrier::complete_tx::bytes "
        "[%0], [%1], %2, [%3];"
        :: "r"(dst), "l"(src), "r"(bytes), "r"(mbar) : "memory");
}
#define MBAR_INIT(addr, cnt) \
    asm volatile("mbarrier.init.shared.b64 [%0], %1;" :: "r"(addr), "r"(cnt) : "memory")
#define MBAR_EXPECT(addr, n) \
    asm volatile("mbarrier.arrive.expect_tx.shared.b64 _, [%0], %1;" :: "r"(addr), "r"(n) : "memory")
#define MBAR_WAIT(addr, parity) do {                                            \
    uint32_t _m = (addr), _p = (parity), _d;                                    \
    asm volatile("{\n\t.reg .pred p;\n\t"                                       \
        "mbarrier.try_wait.parity.acquire.cta.shared::cta.b64 p, [%1], %2;\n\t" \
        "selp.b32 %0, 1, 0, p;\n\t}" : "=r"(_d) : "r"(_m), "r"(_p) : "memory"); \
    if (!_d) {                                                                  \
        asm volatile("{\n\t.reg .pred P1;\n\t"                                  \
            "W_%=:\n\t"                                                         \
            "mbarrier.try_wait.parity.acquire.cta.shared::cta.b64 P1, [%0], %1, 0x989680;\n\t" \
            "@P1 bra.uni D_%=;\n\t"                                             \
            "bra.uni W_%=;\n\t"                                                 \
            "D_%=:\n\t}" :: "r"(_m), "r"(_p) : "memory");                       \
    }                                                                           \
} while (0)

__device__ __forceinline__ void mma_f16(float* c, const uint32_t* a, const uint32_t* b) {
    asm volatile(
        "mma.sync.aligned.m16n8k16.row.col.f32.f16.f16.f32 "
        "{%0,%1,%2,%3}, {%4,%5,%6,%7}, {%8,%9}, {%0,%1,%2,%3};"
        : "+f"(c[0]), "+f"(c[1]), "+f"(c[2]), "+f"(c[3])
        : "r"(a[0]), "r"(a[1]), "r"(a[2]), "r"(a[3]), "r"(b[0]), "r"(b[1]));
}
__device__ __forceinline__ void ldmatrix_x4(uint32_t* r, uint32_t addr) {
    asm volatile("ldmatrix.sync.aligned.m8n8.x4.shared.b16 {%0,%1,%2,%3}, [%4];"
                 : "=r"(r[0]), "=r"(r[1]), "=r"(r[2]), "=r"(r[3]) : "r"(addr));
}

// ---------------------------------------------------------------------------
// Kernel 0: repack W1 [K][N] f32 -> g_w1b: per-32k-tile 16KB swizzled blocks.
// Two consecutive blocks form one 64-k GEMM tile (single 32KB bulk copy).
// half (n,k32) -> blk + line(n>>1)*128 + (((n&1)*4 + k/8) ^ (line&7))*16 + (k&7)*2
// ---------------------------------------------------------------------------
__global__ void repack_w1_kernel(const float* __restrict__ W1) {
    const int kt = blockIdx.x;        // 0..593 (32-k tiles)
    const int n  = threadIdx.x;       // 0..255
    const int kb = kt * 32;
    const int line = n >> 1, h = n & 1;
    char* base = (char*)g_w1b + (size_t)kt * B_BLK32;
#pragma unroll
    for (int c = 0; c < 4; c++) {
        uint32_t w[4];
#pragma unroll
        for (int j = 0; j < 4; j++) {
            int k0 = kb + c * 8 + j * 2;
            float v0 = (k0     < KTOT) ? W1[(size_t)k0 * SD + n]       : 0.f;
            float v1 = (k0 + 1 < KTOT) ? W1[(size_t)(k0 + 1) * SD + n] : 0.f;
            w[j] = pack_f16x2(v1, v0);
        }
        uint32_t off = line * 128 + ((((h << 2) + c) ^ (line & 7)) << 4);
        *(uint4*)(base + off) = make_uint4(w[0], w[1], w[2], w[3]);
    }
}

// ---------------------------------------------------------------------------
// GEMM: stream-K fp16 m16n8k16, BK=64; A per-thread cp.async, B bulk copy.
// Stage/parity derived from the global tile sequence on BOTH sides:
//   stage(q) = q % 3, parity(q) = (q / 3) & 1
// ---------------------------------------------------------------------------
#define LOAD_FRAGS2(As, bsb, s, aarr, barr) do {                               \
    const int _q2 = (lane & 3) * 2;                                            \
    _Pragma("unroll")                                                          \
    for (int mi = 0; mi < 2; mi++) {                                           \
        const int _base = (wrow + mi * 16 + (lane >> 2)) * A_ST + (s) * 16 + _q2; \
        float2 _v0 = *(const float2*)&(As)[_base];                             \
        float2 _v1 = *(const float2*)&(As)[_base + 8 * A_ST];                  \
        float2 _v2 = *(const float2*)&(As)[_base + 8];                         \
        float2 _v3 = *(const float2*)&(As)[_base + 8 * A_ST + 8];              \
        (aarr)[mi][0] = pack_f16x2(_v0.y, _v0.x);                              \
        (aarr)[mi][1] = pack_f16x2(_v1.y, _v1.x);                              \
        (aarr)[mi][2] = pack_f16x2(_v2.y, _v2.x);                              \
        (aarr)[mi][3] = pack_f16x2(_v3.y, _v3.x);                              \
    }                                                                          \
    const int _g  = lane >> 3;                                                 \
    const int _nrb = (lane & 7) + ((_g >> 1) << 3);                            \
    const int _ci = (s) * 2 + (_g & 1);        /* 16B k-chunk 0..7 */          \
    _Pragma("unroll")                                                          \
    for (int j = 0; j < 4; j++) {                                              \
        const int _n  = wcol + j * 16 + _nrb;                                  \
        const int _ln = _n >> 1;                                               \
        uint32_t _addr = (bsb) + ((_ci >> 2) << 14) + _ln * 128 +              \
                         (((((_n & 1) << 2) + (_ci & 3)) ^ (_ln & 7)) << 4);   \
        uint32_t _r[4];                                                        \
        ldmatrix_x4(_r, _addr);                                                \
        (barr)[2*j  ][0] = _r[0]; (barr)[2*j  ][1] = _r[1];                    \
        (barr)[2*j+1][0] = _r[2]; (barr)[2*j+1][1] = _r[3];                    \
    }                                                                          \
} while (0)

__global__ __launch_bounds__(512, 1)
void gemm_f16_kernel(const float* __restrict__ x, const float* __restrict__ b1)
{
    extern __shared__ char smem[];
    const uint32_t sb = smem_u32(smem);

    const int tid  = threadIdx.x;
    const int lane = tid & 31;
    const int wid  = tid >> 5;
    const int wrow = (wid & 3) * 32;
    const int wcol = (wid >> 2) * 64;

    if (tid == 0) {
#pragma unroll
        for (int s = 0; s < 3; s++) MBAR_INIT(sb + MB_OFF + s * 8, 1);
    }
    __syncthreads();

    const int c = blockIdx.x;
    int wbeg = c * PERC;
    const int wcap = min(wbeg + PERC, TOTW);
    int tseq = 0;   // global tile sequence across fragments

    while (wbeg < wcap) {
        const int m      = wbeg / KT_PER_M;
        const int kt0    = wbeg - m * KT_PER_M;
        const int fend   = min(wcap, (m + 1) * KT_PER_M);
        const int nt     = fend - wbeg;
        const int slot   = c - (KT_PER_M * m) / PERC;
        const bool addb  = (kt0 == 0);
        const int m0     = m * BM;

        float acc[2][8][4];
#pragma unroll
        for (int mi = 0; mi < 2; mi++)
#pragma unroll
            for (int ni = 0; ni < 8; ni++)
#pragma unroll
                for (int j = 0; j < 4; j++) acc[mi][ni][j] = 0.f;

        __syncthreads();   // all warps done with previous fragment's smem

        auto load_a = [&](int kt, int stage) {
            const uint32_t ab = sb + stage * STAGE_BYTES;
            const int kb = kt * BK;
#pragma unroll
            for (int i = 0; i < 4; i++) {
                int cc  = tid + i * 512;            // 0..2047
                int row = cc >> 4;                  // 0..127
                int ko  = (cc & 15) << 2;           // 0..60
                int kg  = kb + ko;
                cp_async16(ab + row * (A_ST * 4) + ko * 4,
                           x + (size_t)(m0 + row) * KTOT + kg, kg < KTOT);
            }
        };
        auto load_b = [&](int kt, int stage) {      // tid 0 only
            const uint32_t bbs = sb + stage * STAGE_BYTES + STAGE_A_BYTES;
            const uint32_t mb  = sb + MB_OFF + stage * 8;
            MBAR_EXPECT(mb, B_BLK);
            cp_bulk(bbs, (const char*)g_w1b + (size_t)kt * B_BLK, B_BLK, mb);
        };

        // prologue: 2 tiles in flight; stage from global sequence
#pragma unroll
        for (int i = 0; i < 2; i++) {
            const int st = (tseq + i) % 3;
            if (i < nt) {
                load_a(kt0 + i, st);
                if (tid == 0) load_b(kt0 + i, st);
            }
            CP_COMMIT();
        }

        for (int t = 0; t < nt; t++) {
            const int q  = tseq + t;
            const int st = q % 3;
            MBAR_WAIT(sb + MB_OFF + st * 8, (q / 3) & 1);
            CP_WAIT1();
            __syncthreads();

            if (t + 2 < nt) {
                const int st2 = (q + 2) % 3;
                load_a(kt0 + t + 2, st2);
                if (tid == 0) load_b(kt0 + t + 2, st2);
            }
            CP_COMMIT();

            const float* As = (const float*)(smem + st * STAGE_BYTES);
            const uint32_t bsb = sb + st * STAGE_BYTES + STAGE_A_BYTES;

            uint32_t af[2][2][4], bf[2][8][2];
            LOAD_FRAGS2(As, bsb, 0, af[0], bf[0]);
#pragma unroll
            for (int s = 0; s < 4; s++) {
                const int cur = s & 1;
                if (s < 3) LOAD_FRAGS2(As, bsb, s + 1, af[cur ^ 1], bf[cur ^ 1]);
#pragma unroll
                for (int mi = 0; mi < 2; mi++)
#pragma unroll
                    for (int ni = 0; ni < 8; ni++)
                        mma_f16(acc[mi][ni], af[cur][mi], bf[cur][ni]);
            }
        }
        tseq += nt;

        float* op = g_hp[slot];
#pragma unroll
        for (int mi = 0; mi < 2; mi++) {
            int r0 = m0 + wrow + mi * 16 + (lane >> 2);
#pragma unroll
            for (int ni = 0; ni < 8; ni++) {
                int cc = wcol + ni * 8 + (lane & 3) * 2;
                float bx = 0.f, by = 0.f;
                if (addb) { bx = __ldg(&b1[cc]); by = __ldg(&b1[cc + 1]); }
                float2 v0 = make_float2(acc[mi][ni][0] + bx, acc[mi][ni][1] + by);
                float2 v1 = make_float2(acc[mi][ni][2] + bx, acc[mi][ni][3] + by);
                *(float2*)(op + (size_t)r0 * SD + cc)       = v0;
                *(float2*)(op + (size_t)(r0 + 8) * SD + cc) = v1;
            }
        }
        wbeg = fend;
    }
}

// ---------------------------------------------------------------------------
// Kernel 2: per-sample pathway expert + drug head.
// ---------------------------------------------------------------------------
__global__ __launch_bounds__(128)
void pathway_drug_kernel(const float* __restrict__ Wp,
                         const float* __restrict__ bp,
                         const float* __restrict__ Wd,
                         const float* __restrict__ bd,
                         const int*   __restrict__ drug_indices,
                         const int*   __restrict__ drug_to_pw,
                         float*       __restrict__ out)
{
    const int b   = blockIdx.x;
    const int tid = threadIdx.x;

    __shared__ float hs[SD];
    __shared__ float red[4];

    const int drug = drug_indices[b];
    const int p    = drug_to_pw[drug];

    const int m  = b >> 7;
    const int c0 = (KT_PER_M * m) / PERC;
    const int c1 = (KT_PER_M * (m + 1) - 1) / PERC;
    const int ns = c1 - c0 + 1;                    // 3 or 4

    {
        const size_t i0 = (size_t)b * SD + tid;
        float h0 = g_hp[0][i0]       + g_hp[1][i0]       + g_hp[2][i0];
        float h1 = g_hp[0][i0 + 128] + g_hp[1][i0 + 128] + g_hp[2][i0 + 128];
        if (ns == 4) { h0 += g_hp[3][i0]; h1 += g_hp[3][i0 + 128]; }
        hs[tid]       = fmaxf(h0, 0.f);
        hs[tid + 128] = fmaxf(h1, 0.f);
    }
    __syncthreads();

    const float* wcol = Wp + (size_t)p * SD * PDD + tid;
    float acc = 0.f;
#pragma unroll 8
    for (int s = 0; s < SD; s++)
        acc = fmaf(hs[s], wcol[(size_t)s * PDD], acc);

    acc += bp[p * PDD + tid];
    acc = fmaxf(acc, 0.f);

    float v = acc * Wd[drug * PDD + tid];
#pragma unroll
    for (int off = 16; off > 0; off >>= 1)
        v += __shfl_xor_sync(0xffffffffu, v, off);
    if ((tid & 31) == 0) red[tid >> 5] = v;
    __syncthreads();
    if (tid == 0)
        out[b] = red[0] + red[1] + red[2] + red[3] + bd[drug];
}

// ---------------------------------------------------------------------------
// Launch. Inputs: x, drug_indices, W1, b1, Wp, bp, Wd, bd, drug_to_pw
// ---------------------------------------------------------------------------
extern "C" void kernel_launch(void* const* d_in, const int* in_sizes, int n_in,
                              void* d_out, int out_size)
{
    const float* x            = (const float*)d_in[0];
    const int*   drug_indices = (const int*)  d_in[1];
    const float* W1           = (const float*)d_in[2];
    const float* b1           = (const float*)d_in[3];
    const float* Wp           = (const float*)d_in[4];
    const float* bp           = (const float*)d_in[5];
    const float* Wd           = (const float*)d_in[6];
    const float* bd           = (const float*)d_in[7];
    const int*   drug_to_pw   = (const int*)  d_in[8];
    float*       out          = (float*)d_out;

    static int attr_set = 0;
    if (!attr_set) {
        cudaFuncSetAttribute(gemm_f16_kernel,
                             cudaFuncAttributeMaxDynamicSharedMemorySize, SMEM_GEMM);
        attr_set = 1;
    }

    repack_w1_kernel<<<KT_PER_M * 2, 256>>>(W1);

    gemm_f16_kernel<<<GRID_GEMM, 512, SMEM_GEMM>>>(x, b1);

    pathway_drug_kernel<<<BB, 128>>>(Wp, bp, Wd, bd, drug_indices, drug_to_pw, out);
}